// round 11
// baseline (speedup 1.0000x reference)
#include <cuda_runtime.h>
#include <cuda_bf16.h>
#include <cstdint>

#define S_LEN  4096
#define DMODEL 1024
#define NH     16
#define DK     64

// ---------------------------------------------------------------------------
// Scratch (__device__ globals only)
// ---------------------------------------------------------------------------
#define ACT_BYTES (S_LEN * DMODEL * 2)
#define W_BYTES   (DMODEL * DMODEL * 2)

__device__ float g_v[S_LEN * DMODEL];                 // fp32 V from QKV gemm
__device__ __align__(16) char g_Ahi[3][ACT_BYTES];    // converted inputs q,k,v
__device__ __align__(16) char g_Alo[3][ACT_BYTES];
__device__ __align__(16) char g_Whi[4][W_BYTES];      // converted weights
__device__ __align__(16) char g_Wlo[4][W_BYTES];
__device__ __align__(16) char g_Qphi[ACT_BYTES];      // projected Q hi/lo tiles
__device__ __align__(16) char g_Qplo[ACT_BYTES];
__device__ __align__(16) char g_Kphi[ACT_BYTES];      // projected K hi/lo tiles
__device__ __align__(16) char g_Kplo[ACT_BYTES];
__device__ __align__(16) char g_VThi[ACT_BYTES];      // V^T hi/lo tiles
__device__ __align__(16) char g_VTlo[ACT_BYTES];
__device__ __align__(16) char g_atthi[ACT_BYTES];     // attention out hi/lo tiles
__device__ __align__(16) char g_attlo[ACT_BYTES];

// ---------------------------------------------------------------------------
// PTX helpers (baseline PTX only)
// ---------------------------------------------------------------------------
__device__ __forceinline__ uint32_t smem_u32(const void* p) {
    uint32_t a;
    asm("{ .reg .u64 t; cvta.to.shared.u64 t, %1; cvt.u32.u64 %0, t; }"
        : "=r"(a) : "l"(p));
    return a;
}
__device__ __forceinline__ void mbar_init(uint32_t bar, uint32_t cnt) {
    asm volatile("mbarrier.init.shared.b64 [%0], %1;" :: "r"(bar), "r"(cnt) : "memory");
}
__device__ __forceinline__ void mbar_expect_tx(uint32_t bar, uint32_t bytes) {
    asm volatile("mbarrier.arrive.expect_tx.shared.b64 _, [%0], %1;"
                 :: "r"(bar), "r"(bytes) : "memory");
}
__device__ __forceinline__ void mbar_wait(uint32_t bar, uint32_t parity) {
    asm volatile(
        "{\n\t.reg .pred P;\n"
        "W_%=:\n\t"
        "mbarrier.try_wait.parity.acquire.cta.shared::cta.b64 P, [%0], %1, 0x989680;\n\t"
        "@P bra D_%=;\n\t"
        "bra W_%=;\n"
        "D_%=:\n\t}"
        :: "r"(bar), "r"(parity) : "memory");
}
__device__ __forceinline__ void bulk_g2s(uint32_t dst, const void* src, uint32_t bytes,
                                         uint32_t bar) {
    asm volatile(
        "cp.async.bulk.shared::cluster.global.mbarrier::complete_tx::bytes "
        "[%0], [%1], %2, [%3];"
        :: "r"(dst), "l"(src), "r"(bytes), "r"(bar) : "memory");
}
__device__ __forceinline__ void ldsm_x4(uint32_t& r0, uint32_t& r1, uint32_t& r2,
                                        uint32_t& r3, uint32_t addr) {
    asm volatile("ldmatrix.sync.aligned.m8n8.x4.shared.b16 {%0,%1,%2,%3}, [%4];"
                 : "=r"(r0), "=r"(r1), "=r"(r2), "=r"(r3) : "r"(addr));
}
#define MMA_BF16(acc, a, b)                                                   \
    asm volatile(                                                             \
        "mma.sync.aligned.m16n8k16.row.col.f32.bf16.bf16.f32 "                \
        "{%0,%1,%2,%3}, {%4,%5,%6,%7}, {%8,%9}, {%0,%1,%2,%3};"               \
        : "+f"((acc)[0]), "+f"((acc)[1]), "+f"((acc)[2]), "+f"((acc)[3])      \
        : "r"((a)[0]), "r"((a)[1]), "r"((a)[2]), "r"((a)[3]),                 \
          "r"((b)[0]), "r"((b)[1]))

__device__ __forceinline__ float ex2(float x) {
    float r;
    asm("ex2.approx.f32 %0, %1;" : "=f"(r) : "f"(x));
    return r;
}
__device__ __forceinline__ void split2(float a, float b, uint32_t& hi, uint32_t& lo) {
    __nv_bfloat16 ha = __float2bfloat16(a), hb = __float2bfloat16(b);
    float ra = a - __bfloat162float(ha);
    float rb = b - __bfloat162float(hb);
    __nv_bfloat162 H; H.x = ha; H.y = hb;
    __nv_bfloat162 L = __floats2bfloat162_rn(ra, rb);
    hi = *(uint32_t*)&H;
    lo = *(uint32_t*)&L;
}

// ---------------------------------------------------------------------------
// Conversion: fp32 [rows x 1024] -> bf16 hi/lo SW128-swizzled [128x64] tiles
// ---------------------------------------------------------------------------
struct ConvArgs {
    const float* src[4];
    char* hi[4];
    char* lo[4];
};

__global__ __launch_bounds__(256)
void conv_kernel(ConvArgs a, int rows)
{
    const float* src = a.src[blockIdx.y];
    char* hip = a.hi[blockIdx.y];
    char* lop = a.lo[blockIdx.y];

    const int idx = blockIdx.x * 256 + threadIdx.x;
    const int m  = idx >> 7;
    const int k0 = (idx & 127) << 3;

    const float* p = src + (size_t)m * DMODEL + k0;
    float4 x0 = *(const float4*)p;
    float4 x1 = *(const float4*)(p + 4);
    float xs[8] = {x0.x, x0.y, x0.z, x0.w, x1.x, x1.y, x1.z, x1.w};

    uint32_t uh[4], ul[4];
#pragma unroll
    for (int i = 0; i < 4; i++) split2(xs[2 * i], xs[2 * i + 1], uh[i], ul[i]);

    const size_t tile = ((size_t)(m >> 7) * 16 + (k0 >> 6)) * 16384;
    uint32_t inner = (uint32_t)((m & 127) * 128 + (k0 & 63) * 2);
    inner ^= (inner >> 3) & 0x70;

    *(uint4*)(hip + tile + inner) = make_uint4(uh[0], uh[1], uh[2], uh[3]);
    *(uint4*)(lop + tile + inner) = make_uint4(ul[0], ul[1], ul[2], ul[3]);
}

// ---------------------------------------------------------------------------
// V^T tiles
// ---------------------------------------------------------------------------
__global__ __launch_bounds__(256)
void conv_vt_kernel(const float* __restrict__ V,
                    char* __restrict__ VTh, char* __restrict__ VTl)
{
    __shared__ float smv[64][65];
    const int jc = blockIdx.x, h = blockIdx.y;
    const int tid = threadIdx.x;

    for (int idx = tid; idx < 64 * 16; idx += 256) {
        const int j = idx >> 4, c4 = (idx & 15) * 4;
        float4 x = *(const float4*)&V[(size_t)(jc * 64 + j) * DMODEL + h * 64 + c4];
        smv[j][c4 + 0] = x.x; smv[j][c4 + 1] = x.y;
        smv[j][c4 + 2] = x.z; smv[j][c4 + 3] = x.w;
    }
    __syncthreads();

    const size_t tbase = ((size_t)h * 64 + jc) * 8192;
    for (int idx = tid; idx < 512; idx += 256) {
        const int d = idx >> 3, jb = (idx & 7) * 8;
        uint32_t hi[4], lo[4];
#pragma unroll
        for (int p = 0; p < 4; p++)
            split2(smv[jb + 2 * p][d], smv[jb + 2 * p + 1][d], hi[p], lo[p]);
        uint32_t inner = (uint32_t)(d * 128 + jb * 2);
        inner ^= (inner >> 3) & 0x70;
        *(uint4*)(VTh + tbase + inner) = make_uint4(hi[0], hi[1], hi[2], hi[3]);
        *(uint4*)(VTl + tbase + inner) = make_uint4(lo[0], lo[1], lo[2], lo[3]);
    }
}

// ---------------------------------------------------------------------------
// mma.sync GEMM, bf16x3 split, 3-stage pipeline, copy issued 2 chunks ahead.
// ---------------------------------------------------------------------------
struct GemmArgs {
    const char* Ah[3]; const char* Al[3];
    const char* Bh[3]; const char* Bl[3];
    const float* bias[3];
    float* Cf[3];
    char* Chi[3]; char* Clo[3];
    int modeB[3];
};

#define TILE_B      16384
#define STAGE_B     (4 * TILE_B)
#define NSTAGE      3
#define NCHUNK      16
#define SM_FULL     8
#define SM_BIAS     512
#define SM_STAGE    1024
#define GEMM_SMEM   (SM_STAGE + NSTAGE * STAGE_B)   // 197632

__device__ __forceinline__ void gemm_issue(uint32_t dst, uint32_t bar,
                                           const char* Ah, const char* Al,
                                           const char* Bh, const char* Bl, int c)
{
    mbar_expect_tx(bar, STAGE_B);
    const size_t off = (size_t)c * TILE_B;
    bulk_g2s(dst + 0 * TILE_B, Ah + off, TILE_B, bar);
    bulk_g2s(dst + 1 * TILE_B, Al + off, TILE_B, bar);
    bulk_g2s(dst + 2 * TILE_B, Bh + off, TILE_B, bar);
    bulk_g2s(dst + 3 * TILE_B, Bl + off, TILE_B, bar);
}

__global__ __launch_bounds__(256, 1)
void gemm_tc_kernel(GemmArgs g)
{
    extern __shared__ char sm[];
    const uint32_t smb = smem_u32(sm);
    const int tid = threadIdx.x;
    const int wid = tid >> 5;
    const int l   = tid & 31;
    const int z = blockIdx.z;

    const char* Ah = g.Ah[z] + (size_t)blockIdx.y * (NCHUNK * TILE_B);
    const char* Al = g.Al[z] + (size_t)blockIdx.y * (NCHUNK * TILE_B);
    const char* Bh = g.Bh[z] + (size_t)blockIdx.x * (NCHUNK * TILE_B);
    const char* Bl = g.Bl[z] + (size_t)blockIdx.x * (NCHUNK * TILE_B);
    const int n0 = blockIdx.x * 128;
    const int m0 = blockIdx.y * 128;

    if (tid == 0) {
        mbar_init(smb + SM_FULL + 0, 1);
        mbar_init(smb + SM_FULL + 8, 1);
        mbar_init(smb + SM_FULL + 16, 1);
    }
    if (tid < 128) ((float*)(sm + SM_BIAS))[tid] = g.bias[z][n0 + tid];
    __syncthreads();

    if (tid == 0) {
#pragma unroll
        for (int p = 0; p < 2; p++)
            gemm_issue(smb + SM_STAGE + p * STAGE_B, smb + SM_FULL + p * 8,
                       Ah, Al, Bh, Bl, p);
    }

    const int wm = wid & 1;
    const int wn = wid >> 1;
    const uint32_t sw = (uint32_t)((l & 7) << 4);
    const int a_row = wm * 64 + (l & 7) + ((l >> 3) & 1) * 8;
    const uint32_t a_ksel = ((l >> 4) & 1) * 16;
    const int b_row = wn * 32 + (l & 7) + ((l >> 4) & 1) * 8;
    const uint32_t b_ksel = ((l >> 3) & 1) * 16;

    float acc[4][4][4];
#pragma unroll
    for (int f = 0; f < 4; f++)
#pragma unroll
        for (int gg = 0; gg < 4; gg++)
#pragma unroll
            for (int e = 0; e < 4; e++) acc[f][gg][e] = 0.f;

    for (int s = 0; s < NCHUNK; s++) {
        const int st = s % NSTAGE;
        __syncthreads();    // all warps drained stage (s+2)%NSTAGE (chunk s-1)
        if (tid == 0 && s + 2 < NCHUNK) {
            const int t2 = (s + 2) % NSTAGE;
            gemm_issue(smb + SM_STAGE + t2 * STAGE_B, smb + SM_FULL + t2 * 8,
                       Ah, Al, Bh, Bl, s + 2);
        }
        mbar_wait(smb + SM_FULL + st * 8, (uint32_t)((s / NSTAGE) & 1));

        const uint32_t base = smb + SM_STAGE + st * STAGE_B;
        const uint32_t bAh = base;
        const uint32_t bAl = base + TILE_B;
        const uint32_t bBh = base + 2 * TILE_B;
        const uint32_t bBl = base + 3 * TILE_B;

#pragma unroll
        for (int s4 = 0; s4 < 4; s4++) {
            const uint32_t kbA = (uint32_t)(s4 * 32) + a_ksel;
            const uint32_t kbB = (uint32_t)(s4 * 32) + b_ksel;

            uint32_t ah[4][4], al[4][4], bh[4][2], bl[4][2];
#pragma unroll
            for (int f = 0; f < 4; f++) {
                const uint32_t ro = (uint32_t)(a_row + f * 16) * 128;
                ldsm_x4(ah[f][0], ah[f][1], ah[f][2], ah[f][3], bAh + ro + (kbA ^ sw));
                ldsm_x4(al[f][0], al[f][1], al[f][2], al[f][3], bAl + ro + (kbA ^ sw));
            }
#pragma unroll
            for (int gg = 0; gg < 2; gg++) {
                const uint32_t ro = (uint32_t)(b_row + gg * 16) * 128;
                ldsm_x4(bh[2 * gg][0], bh[2 * gg][1], bh[2 * gg + 1][0], bh[2 * gg + 1][1],
                        bBh + ro + (kbB ^ sw));
                ldsm_x4(bl[2 * gg][0], bl[2 * gg][1], bl[2 * gg + 1][0], bl[2 * gg + 1][1],
                        bBl + ro + (kbB ^ sw));
            }
#pragma unroll
            for (int f = 0; f < 4; f++)
#pragma unroll
                for (int gg = 0; gg < 4; gg++) {
                    MMA_BF16(acc[f][gg], ah[f], bh[gg]);
                    MMA_BF16(acc[f][gg], ah[f], bl[gg]);
                    MMA_BF16(acc[f][gg], al[f], bh[gg]);
                }
        }
    }

    // epilogue
    const float* sb = (const float*)(sm + SM_BIAS);
    const int gid = l >> 2;
    const int tig = l & 3;

    if (g.modeB[z]) {
        char* oh = g.Chi[z];
        char* ol = g.Clo[z];
        const size_t tbase = (size_t)blockIdx.y * 16 * 16384;
#pragma unroll
        for (int f = 0; f < 4; f++) {
            const int lrow0 = wm * 64 + f * 16 + gid;
#pragma unroll
            for (int gg = 0; gg < 4; gg++) {
                const int lcol = wn * 32 + gg * 8 + tig * 2;
                const float b0 = sb[lcol], b1 = sb[lcol + 1];
                const int kch = (n0 + lcol) >> 6;
                const size_t tof = tbase + (size_t)kch * 16384;
                uint32_t h0, l0v, h1, l1v;
                split2(acc[f][gg][0] + b0, acc[f][gg][1] + b1, h0, l0v);
                split2(acc[f][gg][2] + b0, acc[f][gg][3] + b1, h1, l1v);
                uint32_t in0 = (uint32_t)(lrow0 * 128 + (lcol & 63) * 2);
                in0 ^= (in0 >> 3) & 0x70;
                uint32_t in1 = (uint32_t)((lrow0 + 8) * 128 + (lcol & 63) * 2);
                in1 ^= (in1 >> 3) & 0x70;
                *(uint32_t*)(oh + tof + in0) = h0;
                *(uint32_t*)(ol + tof + in0) = l0v;
                *(uint32_t*)(oh + tof + in1) = h1;
                *(uint32_t*)(ol + tof + in1) = l1v;
            }
        }
    } else {
        float* C = g.Cf[z];
#pragma unroll
        for (int f = 0; f < 4; f++) {
            const int row0 = m0 + wm * 64 + f * 16 + gid;
#pragma unroll
            for (int gg = 0; gg < 4; gg++) {
                const int col = n0 + wn * 32 + gg * 8 + tig * 2;
                const float b0 = sb[col - n0], b1 = sb[col - n0 + 1];
                float2 v0, v1;
                v0.x = acc[f][gg][0] + b0; v0.y = acc[f][gg][1] + b1;
                v1.x = acc[f][gg][2] + b0; v1.y = acc[f][gg][3] + b1;
                *(float2*)&C[(size_t)row0 * DMODEL + col] = v0;
                *(float2*)&C[(size_t)(row0 + 8) * DMODEL + col] = v1;
            }
        }
    }
}

// ---------------------------------------------------------------------------
// Tensor-core local-window flash attention (2-stage: keeps 2 CTAs/SM)
// ---------------------------------------------------------------------------
#define ATT_SMEM (81920 + 64)

__device__ __forceinline__ void attn_issue(uint32_t stagebase, uint32_t bar,
                                           const char* Kh, const char* Kl,
                                           const char* VTh, const char* VTl,
                                           int h, int ks)
{
    mbar_expect_tx(bar, 32768);
    const size_t koff = ((size_t)(ks >> 7) * 16 + h) * 16384 + (size_t)(ks & 64) * 128;
    const size_t voff = ((size_t)h * 64 + (ks >> 6)) * 8192;
    bulk_g2s(stagebase,         Kh + koff, 8192, bar);
    bulk_g2s(stagebase + 8192,  Kl + koff, 8192, bar);
    bulk_g2s(stagebase + 16384, VTh + voff, 8192, bar);
    bulk_g2s(stagebase + 24576, VTl + voff, 8192, bar);
}

__global__ __launch_bounds__(128)
void attn_tc_kernel(const char* __restrict__ Qh, const char* __restrict__ Ql,
                    const char* __restrict__ Kh, const char* __restrict__ Kl,
                    const char* __restrict__ VTh, const char* __restrict__ VTl,
                    char* __restrict__ Ohi, char* __restrict__ Olo)
{
    extern __shared__ char sm[];
    const uint32_t smb = smem_u32(sm);
    const int h  = blockIdx.x;
    const int q0 = blockIdx.y * 64;
    const int tid = threadIdx.x;
    const int w = tid >> 5, l = tid & 31;
    const int r0 = w * 16;

    const uint32_t smQh = smb;
    const uint32_t smQl = smb + 8192;
    const uint32_t smStage = smb + 16384;
    const uint32_t barBase = smb + 81920;

    {
        const size_t qoff = ((size_t)(q0 >> 7) * 16 + h) * 16384 + (size_t)(q0 & 64) * 128;
        const uint4* shp = (const uint4*)(Qh + qoff);
        const uint4* slp = (const uint4*)(Ql + qoff);
        uint4* dh = (uint4*)sm;
        uint4* dl = (uint4*)(sm + 8192);
        for (int i = tid; i < 512; i += 128) { dh[i] = shp[i]; dl[i] = slp[i]; }
    }
    if (tid == 0) { mbar_init(barBase, 1); mbar_init(barBase + 8, 1); }
    __syncthreads();

    const uint32_t sw = (uint32_t)((l & 7) << 4);
    const int a_row = r0 + (l & 7) + ((l >> 3) & 1) * 8;
    const uint32_t a_ksel = ((l >> 4) & 1) * 16;
    const int b_rowb = (l & 7) + ((l >> 4) & 1) * 8;
    const uint32_t b_ksel = ((l >> 3) & 1) * 16;

    uint32_t qfh[4][4], qfl[4][4];
#pragma unroll
    for (int kt = 0; kt < 4; kt++) {
        const uint32_t col = ((uint32_t)(kt * 32) + a_ksel) ^ sw;
        ldsm_x4(qfh[kt][0], qfh[kt][1], qfh[kt][2], qfh[kt][3],
                smQh + (uint32_t)a_row * 128 + col);
        ldsm_x4(qfl[kt][0], qfl[kt][1], qfl[kt][2], qfl[kt][3],
                smQl + (uint32_t)a_row * 128 + col);
    }

    const int c_lo = (q0 < 128) ? (2 - q0 / 64) : 0;
    const int c_hi = min(4, (S_LEN + 64 - q0) / 64);

    if (tid == 0) {
        attn_issue(smStage, barBase, Kh, Kl, VTh, VTl, h, q0 - 128 + 64 * c_lo);
        attn_issue(smStage + 32768, barBase + 8, Kh, Kl, VTh, VTl, h,
                   q0 - 128 + 64 * (c_lo + 1));
    }

    float mr0 = -1e28f, mr1 = -1e28f, lr0 = 0.f, lr1 = 0.f;
    float acc_o[8][4];
#pragma unroll
    for (int df = 0; df < 8; df++)
#pragma unroll
        for (int e = 0; e < 4; e++) acc_o[df][e] = 0.f;

    const int i0 = q0 + r0 + (l >> 2);
    const int i1 = i0 + 8;

    for (int ci = c_lo; ci <= c_hi; ci++) {
        const int st = (ci - c_lo) & 1;
        const uint32_t ph = (uint32_t)(((ci - c_lo) >> 1) & 1);
        const int ks = q0 - 128 + 64 * ci;
        mbar_wait(barBase + st * 8, ph);

        const uint32_t sKh = smStage + (uint32_t)st * 32768;
        const uint32_t sKl = sKh + 8192;
        const uint32_t sVh = sKh + 16384;
        const uint32_t sVl = sKh + 24576;

        float s[8][4];
#pragma unroll
        for (int t = 0; t < 8; t++)
#pragma unroll
            for (int e = 0; e < 4; e++) s[t][e] = 0.f;

#pragma unroll
        for (int kt = 0; kt < 4; kt++) {
            const uint32_t col = ((uint32_t)(kt * 32) + b_ksel) ^ sw;
            uint32_t kh[8][2], kl[8][2];
#pragma unroll
            for (int jg = 0; jg < 4; jg++) {
                const uint32_t ro = (uint32_t)(jg * 16 + b_rowb) * 128;
                ldsm_x4(kh[2 * jg][0], kh[2 * jg][1], kh[2 * jg + 1][0], kh[2 * jg + 1][1],
                        sKh + ro + col);
                ldsm_x4(kl[2 * jg][0], kl[2 * jg][1], kl[2 * jg + 1][0], kl[2 * jg + 1][1],
                        sKl + ro + col);
            }
#pragma unroll
            for (int t = 0; t < 8; t++) {
                MMA_BF16(s[t], qfh[kt], kh[t]);
                MMA_BF16(s[t], qfh[kt], kl[t]);
                MMA_BF16(s[t], qfl[kt], kh[t]);
            }
        }

        const int jb = ks + 2 * (l & 3);
#pragma unroll
        for (int t = 0; t < 8; t++) {
            const int j0 = jb + 8 * t, j1 = j0 + 1;
            s[t][0] = (j0 >= i0 - 127 && j0 <= i0 + 128) ? s[t][0] * 0.125f : -1e30f;
            s[t][1] = (j1 >= i0 - 127 && j1 <= i0 + 128) ? s[t][1] * 0.125f : -1e30f;
            s[t][2] = (j0 >= i1 - 127 && j0 <= i1 + 128) ? s[t][2] * 0.125f : -1e30f;
            s[t][3] = (j1 >= i1 - 127 && j1 <= i1 + 128) ? s[t][3] * 0.125f : -1e30f;
        }

        float mx0 = -1e30f, mx1 = -1e30f;
#pragma unroll
        for (int t = 0; t < 8; t++) {
            mx0 = fmaxf(mx0, fmaxf(s[t][0], s[t][1]));
            mx1 = fmaxf(mx1, fmaxf(s[t][2], s[t][3]));
        }
        mx0 = fmaxf(mx0, __shfl_xor_sync(0xffffffffu, mx0, 1));
        mx0 = fmaxf(mx0, __shfl_xor_sync(0xffffffffu, mx0, 2));
        mx1 = fmaxf(mx1, __shfl_xor_sync(0xffffffffu, mx1, 1));
        mx1 = fmaxf(mx1, __shfl_xor_sync(0xffffffffu, mx1, 2));

        const float mn0 = fmaxf(mr0, mx0);
        const float mn1 = fmaxf(mr1, mx1);
        const float f0 = ex2((mr0 - mn0) * 1.44269504f);
        const float f1 = ex2((mr1 - mn1) * 1.44269504f);
        mr0 = mn0; mr1 = mn1;

        float sum0 = 0.f, sum1 = 0.f;
#pragma unroll
        for (int t = 0; t < 8; t++) {
            s[t][0] = ex2((s[t][0] - mn0) * 1.44269504f); sum0 += s[t][0];
            s[t][1] = ex2((s[t][1] - mn0) * 1.44269504f); sum0 += s[t][1];
            s[t][2] = ex2((s[t][2] - mn1) * 1.44269504f); sum1 += s[t][2];
            s[t][3] = ex2((s[t][3] - mn1) * 1.44269504f); sum1 += s[t][3];
        }
        sum0 += __shfl_xor_sync(0xffffffffu, sum0, 1);
        sum0 += __shfl_xor_sync(0xffffffffu, sum0, 2);
        sum1 += __shfl_xor_sync(0xffffffffu, sum1, 1);
        sum1 += __shfl_xor_sync(0xffffffffu, sum1, 2);
        lr0 = lr0 * f0 + sum0;
        lr1 = lr1 * f1 + sum1;

#pragma unroll
        for (int df = 0; df < 8; df++) {
            acc_o[df][0] *= f0; acc_o[df][1] *= f0;
            acc_o[df][2] *= f1; acc_o[df][3] *= f1;
        }

#pragma unroll
        for (int jt = 0; jt < 4; jt++) {
            uint32_t aPh[4], aPl[4];
            split2(s[2 * jt][0],     s[2 * jt][1],     aPh[0], aPl[0]);
            split2(s[2 * jt][2],     s[2 * jt][3],     aPh[1], aPl[1]);
            split2(s[2 * jt + 1][0], s[2 * jt + 1][1], aPh[2], aPl[2]);
            split2(s[2 * jt + 1][2], s[2 * jt + 1][3], aPh[3], aPl[3]);

            const uint32_t colv = ((uint32_t)(jt * 32) + b_ksel) ^ sw;
            uint32_t vh[8][2], vl[8][2];
#pragma unroll
            for (int dg = 0; dg < 4; dg++) {
                const uint32_t ro = (uint32_t)(dg * 16 + b_rowb) * 128;
                ldsm_x4(vh[2 * dg][0], vh[2 * dg][1], vh[2 * dg + 1][0], vh[2 * dg + 1][1],
                        sVh + ro + colv);
                ldsm_x4(vl[2 * dg][0], vl[2 * dg][1], vl[2 * dg + 1][0], vl[2 * dg + 1][1],
                        sVl + ro + colv);
            }
#pragma unroll
            for (int df = 0; df < 8; df++) {
                MMA_BF16(acc_o[df], aPh, vh[df]);
                MMA_BF16(acc_o[df], aPh, vl[df]);
                MMA_BF16(acc_o[df], aPl, vh[df]);
            }
        }

        __syncthreads();
        if (tid == 0 && ci + 2 <= c_hi)
            attn_issue(smStage + (uint32_t)st * 32768, barBase + st * 8,
                       Kh, Kl, VTh, VTl, h, q0 - 128 + 64 * (ci + 2));
    }

    const float inv0 = 1.f / lr0;
    const float inv1 = 1.f / lr1;
    const size_t obase = ((size_t)(q0 >> 7) * 16 + h) * 16384;
    const int row0 = (q0 & 64) + r0 + (l >> 2);
    const int row1 = row0 + 8;
    const int colb = 2 * (l & 3);

#pragma unroll
    for (int df = 0; df < 8; df++) {
        const int col = df * 8 + colb;
        uint32_t h0, l0v, h1, l1v;
        split2(acc_o[df][0] * inv0, acc_o[df][1] * inv0, h0, l0v);
        split2(acc_o[df][2] * inv1, acc_o[df][3] * inv1, h1, l1v);
        uint32_t in0 = (uint32_t)(row0 * 128 + col * 2);
        in0 ^= (in0 >> 3) & 0x70;
        uint32_t in1 = (uint32_t)(row1 * 128 + col * 2);
        in1 ^= (in1 >> 3) & 0x70;
        *(uint32_t*)(Ohi + obase + in0) = h0;
        *(uint32_t*)(Olo + obase + in0) = l0v;
        *(uint32_t*)(Ohi + obase + in1) = h1;
        *(uint32_t*)(Olo + obase + in1) = l1v;
    }
}

// ---------------------------------------------------------------------------
extern "C" void kernel_launch(void* const* d_in, const int* in_sizes, int n_in,
                              void* d_out, int out_size)
{
    const float* q  = (const float*)d_in[0];
    const float* k  = (const float*)d_in[1];
    const float* v  = (const float*)d_in[2];
    const float* wq = (const float*)d_in[3];
    const float* bq = (const float*)d_in[4];
    const float* wk = (const float*)d_in[5];
    const float* bk = (const float*)d_in[6];
    const float* wv = (const float*)d_in[7];
    const float* bv = (const float*)d_in[8];
    const float* wo = (const float*)d_in[9];
    const float* bo = (const float*)d_in[10];
    float* out = (float*)d_out;

    float* pv;
    char *ahi, *alo, *whi, *wlo;
    char *qphi, *qplo, *kphi, *kplo, *vthi, *vtlo, *athi, *atlo;
    cudaGetSymbolAddress((void**)&pv,   g_v);
    cudaGetSymbolAddress((void**)&ahi,  g_Ahi);
    cudaGetSymbolAddress((void**)&alo,  g_Alo);
    cudaGetSymbolAddress((void**)&whi,  g_Whi);
    cudaGetSymbolAddress((void**)&wlo,  g_Wlo);
    cudaGetSymbolAddress((void**)&qphi, g_Qphi);
    cudaGetSymbolAddress((void**)&qplo, g_Qplo);
    cudaGetSymbolAddress((void**)&kphi, g_Kphi);
    cudaGetSymbolAddress((void**)&kplo, g_Kplo);
    cudaGetSymbolAddress((void**)&vthi, g_VThi);
    cudaGetSymbolAddress((void**)&vtlo, g_VTlo);
    cudaGetSymbolAddress((void**)&athi, g_atthi);
    cudaGetSymbolAddress((void**)&atlo, g_attlo);

    static bool attrs_set = false;
    if (!attrs_set) {
        cudaFuncSetAttribute(gemm_tc_kernel,
                             cudaFuncAttributeMaxDynamicSharedMemorySize, GEMM_SMEM);
        cudaFuncSetAttribute(attn_tc_kernel,
                             cudaFuncAttributeMaxDynamicSharedMemorySize, ATT_SMEM);
        attrs_set = true;
    }

    // 1) convert input activations q,k,v
    ConvArgs ca{};
    ca.src[0] = q; ca.src[1] = k; ca.src[2] = v;
    for (int i = 0; i < 3; i++) { ca.hi[i] = ahi + (size_t)i * ACT_BYTES;
                                  ca.lo[i] = alo + (size_t)i * ACT_BYTES; }
    conv_kernel<<<dim3(S_LEN * 128 / 256, 3), 256>>>(ca, S_LEN);

    // 2) convert weights
    ConvArgs cw{};
    cw.src[0] = wq; cw.src[1] = wk; cw.src[2] = wv; cw.src[3] = wo;
    for (int i = 0; i < 4; i++) { cw.hi[i] = whi + (size_t)i * W_BYTES;
                                  cw.lo[i] = wlo + (size_t)i * W_BYTES; }
    conv_kernel<<<dim3(DMODEL * 128 / 256, 4), 256>>>(cw, DMODEL);

    // 3) QKV projections
    GemmArgs gq{};
    for (int i = 0; i < 3; i++) {
        gq.Ah[i] = ahi + (size_t)i * ACT_BYTES;
        gq.Al[i] = alo + (size_t)i * ACT_BYTES;
        gq.Bh[i] = whi + (size_t)i * W_BYTES;
        gq.Bl[i] = wlo + (size_t)i * W_BYTES;
    }
    gq.bias[0] = bq; gq.bias[1] = bk; gq.bias[2] = bv;
    gq.modeB[0] = 1; gq.Chi[0] = qphi; gq.Clo[0] = qplo;
    gq.modeB[1] = 1; gq.Chi[1] = kphi; gq.Clo[1] = kplo;
    gq.modeB[2] = 0; gq.Cf[2] = pv;
    gemm_tc_kernel<<<dim3(DMODEL / 128, S_LEN / 128, 3), 256, GEMM_SMEM>>>(gq);

    // 4) V -> V^T hi/lo tiles
    conv_vt_kernel<<<dim3(S_LEN / 64, NH), 256>>>(pv, vthi, vtlo);

    // 5) attention
    attn_tc_kernel<<<dim3(NH, S_LEN / 64), 128, ATT_SMEM>>>(
        qphi, qplo, kphi, kplo, vthi, vtlo, athi, atlo);

    // 6) output projection
    GemmArgs go{};
    go.Ah[0] = athi; go.Al[0] = atlo;
    go.Bh[0] = whi + (size_t)3 * W_BYTES;
    go.Bl[0] = wlo + (size_t)3 * W_BYTES;
    go.bias[0] = bo;
    go.modeB[0] = 0; go.Cf[0] = out;
    gemm_tc_kernel<<<dim3(DMODEL / 128, S_LEN / 128, 1), 256, GEMM_SMEM>>>(go);
}

// round 12
// speedup vs baseline: 1.0075x; 1.0075x over previous
#include <cuda_runtime.h>
#include <cuda_bf16.h>
#include <cstdint>

#define S_LEN  4096
#define DMODEL 1024
#define NH     16
#define DK     64

// ---------------------------------------------------------------------------
// Scratch (__device__ globals only)
// ---------------------------------------------------------------------------
#define ACT_BYTES (S_LEN * DMODEL * 2)
#define W_BYTES   (DMODEL * DMODEL * 2)

__device__ float g_v[S_LEN * DMODEL];                 // fp32 V from QKV gemm
__device__ __align__(16) char g_Ahi[3][ACT_BYTES];    // converted inputs q,k,v
__device__ __align__(16) char g_Alo[3][ACT_BYTES];
__device__ __align__(16) char g_Whi[4][W_BYTES];      // converted weights
__device__ __align__(16) char g_Wlo[4][W_BYTES];
__device__ __align__(16) char g_Qphi[ACT_BYTES];      // projected Q hi/lo tiles
__device__ __align__(16) char g_Qplo[ACT_BYTES];
__device__ __align__(16) char g_Kphi[ACT_BYTES];      // projected K hi/lo tiles
__device__ __align__(16) char g_Kplo[ACT_BYTES];
__device__ __align__(16) char g_VThi[ACT_BYTES];      // V^T hi/lo tiles
__device__ __align__(16) char g_VTlo[ACT_BYTES];
__device__ __align__(16) char g_atthi[ACT_BYTES];     // attention out hi/lo tiles
__device__ __align__(16) char g_attlo[ACT_BYTES];

// ---------------------------------------------------------------------------
// PTX helpers (baseline PTX only)
// ---------------------------------------------------------------------------
__device__ __forceinline__ uint32_t smem_u32(const void* p) {
    uint32_t a;
    asm("{ .reg .u64 t; cvta.to.shared.u64 t, %1; cvt.u32.u64 %0, t; }"
        : "=r"(a) : "l"(p));
    return a;
}
__device__ __forceinline__ void mbar_init(uint32_t bar, uint32_t cnt) {
    asm volatile("mbarrier.init.shared.b64 [%0], %1;" :: "r"(bar), "r"(cnt) : "memory");
}
__device__ __forceinline__ void mbar_expect_tx(uint32_t bar, uint32_t bytes) {
    asm volatile("mbarrier.arrive.expect_tx.shared.b64 _, [%0], %1;"
                 :: "r"(bar), "r"(bytes) : "memory");
}
__device__ __forceinline__ void mbar_wait(uint32_t bar, uint32_t parity) {
    asm volatile(
        "{\n\t.reg .pred P;\n"
        "W_%=:\n\t"
        "mbarrier.try_wait.parity.acquire.cta.shared::cta.b64 P, [%0], %1, 0x989680;\n\t"
        "@P bra D_%=;\n\t"
        "bra W_%=;\n"
        "D_%=:\n\t}"
        :: "r"(bar), "r"(parity) : "memory");
}
__device__ __forceinline__ void bulk_g2s(uint32_t dst, const void* src, uint32_t bytes,
                                         uint32_t bar) {
    asm volatile(
        "cp.async.bulk.shared::cluster.global.mbarrier::complete_tx::bytes "
        "[%0], [%1], %2, [%3];"
        :: "r"(dst), "l"(src), "r"(bytes), "r"(bar) : "memory");
}
__device__ __forceinline__ void ldsm_x4(uint32_t& r0, uint32_t& r1, uint32_t& r2,
                                        uint32_t& r3, uint32_t addr) {
    asm volatile("ldmatrix.sync.aligned.m8n8.x4.shared.b16 {%0,%1,%2,%3}, [%4];"
                 : "=r"(r0), "=r"(r1), "=r"(r2), "=r"(r3) : "r"(addr));
}
#define MMA_BF16(acc, a, b)                                                   \
    asm volatile(                                                             \
        "mma.sync.aligned.m16n8k16.row.col.f32.bf16.bf16.f32 "                \
        "{%0,%1,%2,%3}, {%4,%5,%6,%7}, {%8,%9}, {%0,%1,%2,%3};"               \
        : "+f"((acc)[0]), "+f"((acc)[1]), "+f"((acc)[2]), "+f"((acc)[3])      \
        : "r"((a)[0]), "r"((a)[1]), "r"((a)[2]), "r"((a)[3]),                 \
          "r"((b)[0]), "r"((b)[1]))

__device__ __forceinline__ float ex2(float x) {
    float r;
    asm("ex2.approx.f32 %0, %1;" : "=f"(r) : "f"(x));
    return r;
}
__device__ __forceinline__ void split2(float a, float b, uint32_t& hi, uint32_t& lo) {
    __nv_bfloat16 ha = __float2bfloat16(a), hb = __float2bfloat16(b);
    float ra = a - __bfloat162float(ha);
    float rb = b - __bfloat162float(hb);
    __nv_bfloat162 H; H.x = ha; H.y = hb;
    __nv_bfloat162 L = __floats2bfloat162_rn(ra, rb);
    hi = *(uint32_t*)&H;
    lo = *(uint32_t*)&L;
}

// ---------------------------------------------------------------------------
// Conversion: fp32 [rows x 1024] -> bf16 hi/lo SW128-swizzled [128x64] tiles
// ---------------------------------------------------------------------------
struct ConvArgs {
    const float* src[4];
    char* hi[4];
    char* lo[4];
};

__global__ __launch_bounds__(256)
void conv_kernel(ConvArgs a, int rows)
{
    const float* src = a.src[blockIdx.y];
    char* hip = a.hi[blockIdx.y];
    char* lop = a.lo[blockIdx.y];

    const int idx = blockIdx.x * 256 + threadIdx.x;
    const int m  = idx >> 7;
    const int k0 = (idx & 127) << 3;

    const float* p = src + (size_t)m * DMODEL + k0;
    float4 x0 = *(const float4*)p;
    float4 x1 = *(const float4*)(p + 4);
    float xs[8] = {x0.x, x0.y, x0.z, x0.w, x1.x, x1.y, x1.z, x1.w};

    uint32_t uh[4], ul[4];
#pragma unroll
    for (int i = 0; i < 4; i++) split2(xs[2 * i], xs[2 * i + 1], uh[i], ul[i]);

    const size_t tile = ((size_t)(m >> 7) * 16 + (k0 >> 6)) * 16384;
    uint32_t inner = (uint32_t)((m & 127) * 128 + (k0 & 63) * 2);
    inner ^= (inner >> 3) & 0x70;

    *(uint4*)(hip + tile + inner) = make_uint4(uh[0], uh[1], uh[2], uh[3]);
    *(uint4*)(lop + tile + inner) = make_uint4(ul[0], ul[1], ul[2], ul[3]);
}

// ---------------------------------------------------------------------------
// V^T tiles
// ---------------------------------------------------------------------------
__global__ __launch_bounds__(256)
void conv_vt_kernel(const float* __restrict__ V,
                    char* __restrict__ VTh, char* __restrict__ VTl)
{
    __shared__ float smv[64][65];
    const int jc = blockIdx.x, h = blockIdx.y;
    const int tid = threadIdx.x;

    for (int idx = tid; idx < 64 * 16; idx += 256) {
        const int j = idx >> 4, c4 = (idx & 15) * 4;
        float4 x = *(const float4*)&V[(size_t)(jc * 64 + j) * DMODEL + h * 64 + c4];
        smv[j][c4 + 0] = x.x; smv[j][c4 + 1] = x.y;
        smv[j][c4 + 2] = x.z; smv[j][c4 + 3] = x.w;
    }
    __syncthreads();

    const size_t tbase = ((size_t)h * 64 + jc) * 8192;
    for (int idx = tid; idx < 512; idx += 256) {
        const int d = idx >> 3, jb = (idx & 7) * 8;
        uint32_t hi[4], lo[4];
#pragma unroll
        for (int p = 0; p < 4; p++)
            split2(smv[jb + 2 * p][d], smv[jb + 2 * p + 1][d], hi[p], lo[p]);
        uint32_t inner = (uint32_t)(d * 128 + jb * 2);
        inner ^= (inner >> 3) & 0x70;
        *(uint4*)(VTh + tbase + inner) = make_uint4(hi[0], hi[1], hi[2], hi[3]);
        *(uint4*)(VTl + tbase + inner) = make_uint4(lo[0], lo[1], lo[2], lo[3]);
    }
}

// ---------------------------------------------------------------------------
// mma.sync GEMM, bf16x3 split, 3-stage pipeline, copy issued 2 chunks ahead.
// ---------------------------------------------------------------------------
struct GemmArgs {
    const char* Ah[3]; const char* Al[3];
    const char* Bh[3]; const char* Bl[3];
    const float* bias[3];
    float* Cf[3];
    char* Chi[3]; char* Clo[3];
    int modeB[3];
};

#define TILE_B      16384
#define STAGE_B     (4 * TILE_B)
#define NSTAGE      3
#define NCHUNK      16
#define SM_FULL     8
#define SM_BIAS     512
#define SM_STAGE    1024
#define GEMM_SMEM   (SM_STAGE + NSTAGE * STAGE_B)   // 197632

__device__ __forceinline__ void gemm_issue(uint32_t dst, uint32_t bar,
                                           const char* Ah, const char* Al,
                                           const char* Bh, const char* Bl, int c)
{
    mbar_expect_tx(bar, STAGE_B);
    const size_t off = (size_t)c * TILE_B;
    bulk_g2s(dst + 0 * TILE_B, Ah + off, TILE_B, bar);
    bulk_g2s(dst + 1 * TILE_B, Al + off, TILE_B, bar);
    bulk_g2s(dst + 2 * TILE_B, Bh + off, TILE_B, bar);
    bulk_g2s(dst + 3 * TILE_B, Bl + off, TILE_B, bar);
}

__global__ __launch_bounds__(256, 1)
void gemm_tc_kernel(GemmArgs g)
{
    extern __shared__ char sm[];
    const uint32_t smb = smem_u32(sm);
    const int tid = threadIdx.x;
    const int wid = tid >> 5;
    const int l   = tid & 31;
    const int z = blockIdx.z;

    const char* Ah = g.Ah[z] + (size_t)blockIdx.y * (NCHUNK * TILE_B);
    const char* Al = g.Al[z] + (size_t)blockIdx.y * (NCHUNK * TILE_B);
    const char* Bh = g.Bh[z] + (size_t)blockIdx.x * (NCHUNK * TILE_B);
    const char* Bl = g.Bl[z] + (size_t)blockIdx.x * (NCHUNK * TILE_B);
    const int n0 = blockIdx.x * 128;
    const int m0 = blockIdx.y * 128;

    if (tid == 0) {
        mbar_init(smb + SM_FULL + 0, 1);
        mbar_init(smb + SM_FULL + 8, 1);
        mbar_init(smb + SM_FULL + 16, 1);
    }
    if (tid < 128) ((float*)(sm + SM_BIAS))[tid] = g.bias[z][n0 + tid];
    __syncthreads();

    if (tid == 0) {
#pragma unroll
        for (int p = 0; p < 2; p++)
            gemm_issue(smb + SM_STAGE + p * STAGE_B, smb + SM_FULL + p * 8,
                       Ah, Al, Bh, Bl, p);
    }

    const int wm = wid & 1;
    const int wn = wid >> 1;
    const uint32_t sw = (uint32_t)((l & 7) << 4);
    const int a_row = wm * 64 + (l & 7) + ((l >> 3) & 1) * 8;
    const uint32_t a_ksel = ((l >> 4) & 1) * 16;
    const int b_row = wn * 32 + (l & 7) + ((l >> 4) & 1) * 8;
    const uint32_t b_ksel = ((l >> 3) & 1) * 16;

    float acc[4][4][4];
#pragma unroll
    for (int f = 0; f < 4; f++)
#pragma unroll
        for (int gg = 0; gg < 4; gg++)
#pragma unroll
            for (int e = 0; e < 4; e++) acc[f][gg][e] = 0.f;

    for (int s = 0; s < NCHUNK; s++) {
        const int st = s % NSTAGE;
        __syncthreads();    // all warps drained stage (s+2)%NSTAGE (chunk s-1)
        if (tid == 0 && s + 2 < NCHUNK) {
            const int t2 = (s + 2) % NSTAGE;
            gemm_issue(smb + SM_STAGE + t2 * STAGE_B, smb + SM_FULL + t2 * 8,
                       Ah, Al, Bh, Bl, s + 2);
        }
        mbar_wait(smb + SM_FULL + st * 8, (uint32_t)((s / NSTAGE) & 1));

        const uint32_t base = smb + SM_STAGE + st * STAGE_B;
        const uint32_t bAh = base;
        const uint32_t bAl = base + TILE_B;
        const uint32_t bBh = base + 2 * TILE_B;
        const uint32_t bBl = base + 3 * TILE_B;

#pragma unroll
        for (int s4 = 0; s4 < 4; s4++) {
            const uint32_t kbA = (uint32_t)(s4 * 32) + a_ksel;
            const uint32_t kbB = (uint32_t)(s4 * 32) + b_ksel;

            uint32_t ah[4][4], al[4][4], bh[4][2], bl[4][2];
#pragma unroll
            for (int f = 0; f < 4; f++) {
                const uint32_t ro = (uint32_t)(a_row + f * 16) * 128;
                ldsm_x4(ah[f][0], ah[f][1], ah[f][2], ah[f][3], bAh + ro + (kbA ^ sw));
                ldsm_x4(al[f][0], al[f][1], al[f][2], al[f][3], bAl + ro + (kbA ^ sw));
            }
#pragma unroll
            for (int gg = 0; gg < 2; gg++) {
                const uint32_t ro = (uint32_t)(b_row + gg * 16) * 128;
                ldsm_x4(bh[2 * gg][0], bh[2 * gg][1], bh[2 * gg + 1][0], bh[2 * gg + 1][1],
                        bBh + ro + (kbB ^ sw));
                ldsm_x4(bl[2 * gg][0], bl[2 * gg][1], bl[2 * gg + 1][0], bl[2 * gg + 1][1],
                        bBl + ro + (kbB ^ sw));
            }
#pragma unroll
            for (int f = 0; f < 4; f++)
#pragma unroll
                for (int gg = 0; gg < 4; gg++) {
                    MMA_BF16(acc[f][gg], ah[f], bh[gg]);
                    MMA_BF16(acc[f][gg], ah[f], bl[gg]);
                    MMA_BF16(acc[f][gg], al[f], bh[gg]);
                }
        }
    }

    // epilogue
    const float* sb = (const float*)(sm + SM_BIAS);
    const int gid = l >> 2;
    const int tig = l & 3;

    if (g.modeB[z]) {
        char* oh = g.Chi[z];
        char* ol = g.Clo[z];
        const size_t tbase = (size_t)blockIdx.y * 16 * 16384;
#pragma unroll
        for (int f = 0; f < 4; f++) {
            const int lrow0 = wm * 64 + f * 16 + gid;
#pragma unroll
            for (int gg = 0; gg < 4; gg++) {
                const int lcol = wn * 32 + gg * 8 + tig * 2;
                const float b0 = sb[lcol], b1 = sb[lcol + 1];
                const int kch = (n0 + lcol) >> 6;
                const size_t tof = tbase + (size_t)kch * 16384;
                uint32_t h0, l0v, h1, l1v;
                split2(acc[f][gg][0] + b0, acc[f][gg][1] + b1, h0, l0v);
                split2(acc[f][gg][2] + b0, acc[f][gg][3] + b1, h1, l1v);
                uint32_t in0 = (uint32_t)(lrow0 * 128 + (lcol & 63) * 2);
                in0 ^= (in0 >> 3) & 0x70;
                uint32_t in1 = (uint32_t)((lrow0 + 8) * 128 + (lcol & 63) * 2);
                in1 ^= (in1 >> 3) & 0x70;
                *(uint32_t*)(oh + tof + in0) = h0;
                *(uint32_t*)(ol + tof + in0) = l0v;
                *(uint32_t*)(oh + tof + in1) = h1;
                *(uint32_t*)(ol + tof + in1) = l1v;
            }
        }
    } else {
        float* C = g.Cf[z];
#pragma unroll
        for (int f = 0; f < 4; f++) {
            const int row0 = m0 + wm * 64 + f * 16 + gid;
#pragma unroll
            for (int gg = 0; gg < 4; gg++) {
                const int col = n0 + wn * 32 + gg * 8 + tig * 2;
                const float b0 = sb[col - n0], b1 = sb[col - n0 + 1];
                float2 v0, v1;
                v0.x = acc[f][gg][0] + b0; v0.y = acc[f][gg][1] + b1;
                v1.x = acc[f][gg][2] + b0; v1.y = acc[f][gg][3] + b1;
                *(float2*)&C[(size_t)row0 * DMODEL + col] = v0;
                *(float2*)&C[(size_t)(row0 + 8) * DMODEL + col] = v1;
            }
        }
    }
}

// ---------------------------------------------------------------------------
// Tensor-core local-window flash attention (2-stage: keeps 2 CTAs/SM)
// ---------------------------------------------------------------------------
#define ATT_SMEM (81920 + 64)

__device__ __forceinline__ void attn_issue(uint32_t stagebase, uint32_t bar,
                                           const char* Kh, const char* Kl,
                                           const char* VTh, const char* VTl,
                                           int h, int ks)
{
    mbar_expect_tx(bar, 32768);
    const size_t koff = ((size_t)(ks >> 7) * 16 + h) * 16384 + (size_t)(ks & 64) * 128;
    const size_t voff = ((size_t)h * 64 + (ks >> 6)) * 8192;
    bulk_g2s(stagebase,         Kh + koff, 8192, bar);
    bulk_g2s(stagebase + 8192,  Kl + koff, 8192, bar);
    bulk_g2s(stagebase + 16384, VTh + voff, 8192, bar);
    bulk_g2s(stagebase + 24576, VTl + voff, 8192, bar);
}

__global__ __launch_bounds__(128)
void attn_tc_kernel(const char* __restrict__ Qh, const char* __restrict__ Ql,
                    const char* __restrict__ Kh, const char* __restrict__ Kl,
                    const char* __restrict__ VTh, const char* __restrict__ VTl,
                    char* __restrict__ Ohi, char* __restrict__ Olo)
{
    extern __shared__ char sm[];
    const uint32_t smb = smem_u32(sm);
    const int h  = blockIdx.x;
    const int q0 = blockIdx.y * 64;
    const int tid = threadIdx.x;
    const int w = tid >> 5, l = tid & 31;
    const int r0 = w * 16;

    const uint32_t smQh = smb;
    const uint32_t smQl = smb + 8192;
    const uint32_t smStage = smb + 16384;
    const uint32_t barBase = smb + 81920;

    {
        const size_t qoff = ((size_t)(q0 >> 7) * 16 + h) * 16384 + (size_t)(q0 & 64) * 128;
        const uint4* shp = (const uint4*)(Qh + qoff);
        const uint4* slp = (const uint4*)(Ql + qoff);
        uint4* dh = (uint4*)sm;
        uint4* dl = (uint4*)(sm + 8192);
        for (int i = tid; i < 512; i += 128) { dh[i] = shp[i]; dl[i] = slp[i]; }
    }
    if (tid == 0) { mbar_init(barBase, 1); mbar_init(barBase + 8, 1); }
    __syncthreads();

    const uint32_t sw = (uint32_t)((l & 7) << 4);
    const int a_row = r0 + (l & 7) + ((l >> 3) & 1) * 8;
    const uint32_t a_ksel = ((l >> 4) & 1) * 16;
    const int b_rowb = (l & 7) + ((l >> 4) & 1) * 8;
    const uint32_t b_ksel = ((l >> 3) & 1) * 16;

    uint32_t qfh[4][4], qfl[4][4];
#pragma unroll
    for (int kt = 0; kt < 4; kt++) {
        const uint32_t col = ((uint32_t)(kt * 32) + a_ksel) ^ sw;
        ldsm_x4(qfh[kt][0], qfh[kt][1], qfh[kt][2], qfh[kt][3],
                smQh + (uint32_t)a_row * 128 + col);
        ldsm_x4(qfl[kt][0], qfl[kt][1], qfl[kt][2], qfl[kt][3],
                smQl + (uint32_t)a_row * 128 + col);
    }

    const int c_lo = (q0 < 128) ? (2 - q0 / 64) : 0;
    const int c_hi = min(4, (S_LEN + 64 - q0) / 64);

    if (tid == 0) {
        attn_issue(smStage, barBase, Kh, Kl, VTh, VTl, h, q0 - 128 + 64 * c_lo);
        attn_issue(smStage + 32768, barBase + 8, Kh, Kl, VTh, VTl, h,
                   q0 - 128 + 64 * (c_lo + 1));
    }

    float mr0 = -1e28f, mr1 = -1e28f, lr0 = 0.f, lr1 = 0.f;
    float acc_o[8][4];
#pragma unroll
    for (int df = 0; df < 8; df++)
#pragma unroll
        for (int e = 0; e < 4; e++) acc_o[df][e] = 0.f;

    const int i0 = q0 + r0 + (l >> 2);
    const int i1 = i0 + 8;

    for (int ci = c_lo; ci <= c_hi; ci++) {
        const int st = (ci - c_lo) & 1;
        const uint32_t ph = (uint32_t)(((ci - c_lo) >> 1) & 1);
        const int ks = q0 - 128 + 64 * ci;
        mbar_wait(barBase + st * 8, ph);

        const uint32_t sKh = smStage + (uint32_t)st * 32768;
        const uint32_t sKl = sKh + 8192;
        const uint32_t sVh = sKh + 16384;
        const uint32_t sVl = sKh + 24576;

        float s[8][4];
#pragma unroll
        for (int t = 0; t < 8; t++)
#pragma unroll
            for (int e = 0; e < 4; e++) s[t][e] = 0.f;

#pragma unroll
        for (int kt = 0; kt < 4; kt++) {
            const uint32_t col = ((uint32_t)(kt * 32) + b_ksel) ^ sw;
            uint32_t kh[8][2], kl[8][2];
#pragma unroll
            for (int jg = 0; jg < 4; jg++) {
                const uint32_t ro = (uint32_t)(jg * 16 + b_rowb) * 128;
                ldsm_x4(kh[2 * jg][0], kh[2 * jg][1], kh[2 * jg + 1][0], kh[2 * jg + 1][1],
                        sKh + ro + col);
                ldsm_x4(kl[2 * jg][0], kl[2 * jg][1], kl[2 * jg + 1][0], kl[2 * jg + 1][1],
                        sKl + ro + col);
            }
#pragma unroll
            for (int t = 0; t < 8; t++) {
                MMA_BF16(s[t], qfh[kt], kh[t]);
                MMA_BF16(s[t], qfh[kt], kl[t]);
                MMA_BF16(s[t], qfl[kt], kh[t]);
            }
        }

        const int jb = ks + 2 * (l & 3);
#pragma unroll
        for (int t = 0; t < 8; t++) {
            const int j0 = jb + 8 * t, j1 = j0 + 1;
            s[t][0] = (j0 >= i0 - 127 && j0 <= i0 + 128) ? s[t][0] * 0.125f : -1e30f;
            s[t][1] = (j1 >= i0 - 127 && j1 <= i0 + 128) ? s[t][1] * 0.125f : -1e30f;
            s[t][2] = (j0 >= i1 - 127 && j0 <= i1 + 128) ? s[t][2] * 0.125f : -1e30f;
            s[t][3] = (j1 >= i1 - 127 && j1 <= i1 + 128) ? s[t][3] * 0.125f : -1e30f;
        }

        float mx0 = -1e30f, mx1 = -1e30f;
#pragma unroll
        for (int t = 0; t < 8; t++) {
            mx0 = fmaxf(mx0, fmaxf(s[t][0], s[t][1]));
            mx1 = fmaxf(mx1, fmaxf(s[t][2], s[t][3]));
        }
        mx0 = fmaxf(mx0, __shfl_xor_sync(0xffffffffu, mx0, 1));
        mx0 = fmaxf(mx0, __shfl_xor_sync(0xffffffffu, mx0, 2));
        mx1 = fmaxf(mx1, __shfl_xor_sync(0xffffffffu, mx1, 1));
        mx1 = fmaxf(mx1, __shfl_xor_sync(0xffffffffu, mx1, 2));

        const float mn0 = fmaxf(mr0, mx0);
        const float mn1 = fmaxf(mr1, mx1);
        const float f0 = ex2((mr0 - mn0) * 1.44269504f);
        const float f1 = ex2((mr1 - mn1) * 1.44269504f);
        mr0 = mn0; mr1 = mn1;

        float sum0 = 0.f, sum1 = 0.f;
#pragma unroll
        for (int t = 0; t < 8; t++) {
            s[t][0] = ex2((s[t][0] - mn0) * 1.44269504f); sum0 += s[t][0];
            s[t][1] = ex2((s[t][1] - mn0) * 1.44269504f); sum0 += s[t][1];
            s[t][2] = ex2((s[t][2] - mn1) * 1.44269504f); sum1 += s[t][2];
            s[t][3] = ex2((s[t][3] - mn1) * 1.44269504f); sum1 += s[t][3];
        }
        sum0 += __shfl_xor_sync(0xffffffffu, sum0, 1);
        sum0 += __shfl_xor_sync(0xffffffffu, sum0, 2);
        sum1 += __shfl_xor_sync(0xffffffffu, sum1, 1);
        sum1 += __shfl_xor_sync(0xffffffffu, sum1, 2);
        lr0 = lr0 * f0 + sum0;
        lr1 = lr1 * f1 + sum1;

#pragma unroll
        for (int df = 0; df < 8; df++) {
            acc_o[df][0] *= f0; acc_o[df][1] *= f0;
            acc_o[df][2] *= f1; acc_o[df][3] *= f1;
        }

#pragma unroll
        for (int jt = 0; jt < 4; jt++) {
            uint32_t aPh[4], aPl[4];
            split2(s[2 * jt][0],     s[2 * jt][1],     aPh[0], aPl[0]);
            split2(s[2 * jt][2],     s[2 * jt][3],     aPh[1], aPl[1]);
            split2(s[2 * jt + 1][0], s[2 * jt + 1][1], aPh[2], aPl[2]);
            split2(s[2 * jt + 1][2], s[2 * jt + 1][3], aPh[3], aPl[3]);

            const uint32_t colv = ((uint32_t)(jt * 32) + b_ksel) ^ sw;
            uint32_t vh[8][2], vl[8][2];
#pragma unroll
            for (int dg = 0; dg < 4; dg++) {
                const uint32_t ro = (uint32_t)(dg * 16 + b_rowb) * 128;
                ldsm_x4(vh[2 * dg][0], vh[2 * dg][1], vh[2 * dg + 1][0], vh[2 * dg + 1][1],
                        sVh + ro + colv);
                ldsm_x4(vl[2 * dg][0], vl[2 * dg][1], vl[2 * dg + 1][0], vl[2 * dg + 1][1],
                        sVl + ro + colv);
            }
#pragma unroll
            for (int df = 0; df < 8; df++) {
                MMA_BF16(acc_o[df], aPh, vh[df]);
                MMA_BF16(acc_o[df], aPh, vl[df]);
                MMA_BF16(acc_o[df], aPl, vh[df]);
            }
        }

        __syncthreads();
        if (tid == 0 && ci + 2 <= c_hi)
            attn_issue(smStage + (uint32_t)st * 32768, barBase + st * 8,
                       Kh, Kl, VTh, VTl, h, q0 - 128 + 64 * (ci + 2));
    }

    const float inv0 = 1.f / lr0;
    const float inv1 = 1.f / lr1;
    const size_t obase = ((size_t)(q0 >> 7) * 16 + h) * 16384;
    const int row0 = (q0 & 64) + r0 + (l >> 2);
    const int row1 = row0 + 8;
    const int colb = 2 * (l & 3);

#pragma unroll
    for (int df = 0; df < 8; df++) {
        const int col = df * 8 + colb;
        uint32_t h0, l0v, h1, l1v;
        split2(acc_o[df][0] * inv0, acc_o[df][1] * inv0, h0, l0v);
        split2(acc_o[df][2] * inv1, acc_o[df][3] * inv1, h1, l1v);
        uint32_t in0 = (uint32_t)(row0 * 128 + col * 2);
        in0 ^= (in0 >> 3) & 0x70;
        uint32_t in1 = (uint32_t)(row1 * 128 + col * 2);
        in1 ^= (in1 >> 3) & 0x70;
        *(uint32_t*)(Ohi + obase + in0) = h0;
        *(uint32_t*)(Olo + obase + in0) = l0v;
        *(uint32_t*)(Ohi + obase + in1) = h1;
        *(uint32_t*)(Olo + obase + in1) = l1v;
    }
}

// ---------------------------------------------------------------------------
extern "C" void kernel_launch(void* const* d_in, const int* in_sizes, int n_in,
                              void* d_out, int out_size)
{
    const float* q  = (const float*)d_in[0];
    const float* k  = (const float*)d_in[1];
    const float* v  = (const float*)d_in[2];
    const float* wq = (const float*)d_in[3];
    const float* bq = (const float*)d_in[4];
    const float* wk = (const float*)d_in[5];
    const float* bk = (const float*)d_in[6];
    const float* wv = (const float*)d_in[7];
    const float* bv = (const float*)d_in[8];
    const float* wo = (const float*)d_in[9];
    const float* bo = (const float*)d_in[10];
    float* out = (float*)d_out;

    float* pv;
    char *ahi, *alo, *whi, *wlo;
    char *qphi, *qplo, *kphi, *kplo, *vthi, *vtlo, *athi, *atlo;
    cudaGetSymbolAddress((void**)&pv,   g_v);
    cudaGetSymbolAddress((void**)&ahi,  g_Ahi);
    cudaGetSymbolAddress((void**)&alo,  g_Alo);
    cudaGetSymbolAddress((void**)&whi,  g_Whi);
    cudaGetSymbolAddress((void**)&wlo,  g_Wlo);
    cudaGetSymbolAddress((void**)&qphi, g_Qphi);
    cudaGetSymbolAddress((void**)&qplo, g_Qplo);
    cudaGetSymbolAddress((void**)&kphi, g_Kphi);
    cudaGetSymbolAddress((void**)&kplo, g_Kplo);
    cudaGetSymbolAddress((void**)&vthi, g_VThi);
    cudaGetSymbolAddress((void**)&vtlo, g_VTlo);
    cudaGetSymbolAddress((void**)&athi, g_atthi);
    cudaGetSymbolAddress((void**)&atlo, g_attlo);

    static bool attrs_set = false;
    if (!attrs_set) {
        cudaFuncSetAttribute(gemm_tc_kernel,
                             cudaFuncAttributeMaxDynamicSharedMemorySize, GEMM_SMEM);
        cudaFuncSetAttribute(attn_tc_kernel,
                             cudaFuncAttributeMaxDynamicSharedMemorySize, ATT_SMEM);
        attrs_set = true;
    }

    // 1) convert input activations q,k,v
    ConvArgs ca{};
    ca.src[0] = q; ca.src[1] = k; ca.src[2] = v;
    for (int i = 0; i < 3; i++) { ca.hi[i] = ahi + (size_t)i * ACT_BYTES;
                                  ca.lo[i] = alo + (size_t)i * ACT_BYTES; }
    conv_kernel<<<dim3(S_LEN * 128 / 256, 3), 256>>>(ca, S_LEN);

    // 2) convert weights
    ConvArgs cw{};
    cw.src[0] = wq; cw.src[1] = wk; cw.src[2] = wv; cw.src[3] = wo;
    for (int i = 0; i < 4; i++) { cw.hi[i] = whi + (size_t)i * W_BYTES;
                                  cw.lo[i] = wlo + (size_t)i * W_BYTES; }
    conv_kernel<<<dim3(DMODEL * 128 / 256, 4), 256>>>(cw, DMODEL);

    // 3) QKV projections
    GemmArgs gq{};
    for (int i = 0; i < 3; i++) {
        gq.Ah[i] = ahi + (size_t)i * ACT_BYTES;
        gq.Al[i] = alo + (size_t)i * ACT_BYTES;
        gq.Bh[i] = whi + (size_t)i * W_BYTES;
        gq.Bl[i] = wlo + (size_t)i * W_BYTES;
    }
    gq.bias[0] = bq; gq.bias[1] = bk; gq.bias[2] = bv;
    gq.modeB[0] = 1; gq.Chi[0] = qphi; gq.Clo[0] = qplo;
    gq.modeB[1] = 1; gq.Chi[1] = kphi; gq.Clo[1] = kplo;
    gq.modeB[2] = 0; gq.Cf[2] = pv;
    gemm_tc_kernel<<<dim3(DMODEL / 128, S_LEN / 128, 3), 256, GEMM_SMEM>>>(gq);

    // 4) V -> V^T hi/lo tiles
    conv_vt_kernel<<<dim3(S_LEN / 64, NH), 256>>>(pv, vthi, vtlo);

    // 5) attention
    attn_tc_kernel<<<dim3(NH, S_LEN / 64), 128, ATT_SMEM>>>(
        qphi, qplo, kphi, kplo, vthi, vtlo, athi, atlo);

    // 6) output projection
    GemmArgs go{};
    go.Ah[0] = athi; go.Al[0] = atlo;
    go.Bh[0] = whi + (size_t)3 * W_BYTES;
    go.Bl[0] = wlo + (size_t)3 * W_BYTES;
    go.bias[0] = bo;
    go.modeB[0] = 0; go.Cf[0] = out;
    gemm_tc_kernel<<<dim3(DMODEL / 128, S_LEN / 128, 1), 256, GEMM_SMEM>>>(go);
}